// round 6
// baseline (speedup 1.0000x reference)
#include <cuda_runtime.h>
#include <cuda_bf16.h>
#include <stdint.h>

#define NBATCH 8
#define SEQ    4096
#define DIM    256
#define NTOK   (NBATCH * SEQ)                 // 32768
#define PROJ_ELEMS (NTOK * DIM)               // 8388608
#define S_ELEMS ((long long)NBATCH * SEQ * SEQ)

// ---------------- scratch (static device arrays) ---------------------------
// g_S: fp32 scores; softmax overwrites each 4096-float row in place with
// 4096 hi-bf16 + 4096 lo-bf16 of normalized P.
__device__ __align__(16) float          g_S[S_ELEMS];                 // 537 MB
__device__ __align__(16) unsigned short g_wh[3][DIM * DIM];
__device__ __align__(16) unsigned short g_wl[3][DIM * DIM];
__device__ __align__(16) unsigned short g_qh[PROJ_ELEMS], g_ql[PROJ_ELEMS];
__device__ __align__(16) unsigned short g_kh[PROJ_ELEMS], g_kl[PROJ_ELEMS];
__device__ __align__(16) unsigned short g_vth[PROJ_ELEMS], g_vtl[PROJ_ELEMS];

// ---------------- helpers ---------------------------------------------------
__device__ __forceinline__ uint32_t smem_u32(const void* p) {
    uint32_t a;
    asm("{ .reg .u64 t; cvta.to.shared.u64 t, %1; cvt.u32.u64 %0, t; }"
        : "=r"(a) : "l"(p));
    return a;
}

#define CP16(dst, src) \
    asm volatile("cp.async.cg.shared.global [%0], [%1], 16;" \
                 :: "r"(dst), "l"(src) : "memory")
#define CP_COMMIT()  asm volatile("cp.async.commit_group;" ::: "memory")
#define CP_WAIT2()   asm volatile("cp.async.wait_group 2;" ::: "memory")
#define CP_WAIT1()   asm volatile("cp.async.wait_group 1;" ::: "memory")
#define CP_WAIT0()   asm volatile("cp.async.wait_group 0;" ::: "memory")

#define LDSM4(r, addr) \
    asm volatile("ldmatrix.sync.aligned.m8n8.x4.shared.b16 {%0,%1,%2,%3}, [%4];" \
                 : "=r"((r)[0]), "=r"((r)[1]), "=r"((r)[2]), "=r"((r)[3]) \
                 : "r"(addr))

#define MMA(d, a, b) \
    asm volatile("mma.sync.aligned.m16n8k16.row.col.f32.bf16.bf16.f32 " \
                 "{%0,%1,%2,%3},{%4,%5,%6,%7},{%8,%9},{%0,%1,%2,%3};" \
                 : "+f"((d)[0]), "+f"((d)[1]), "+f"((d)[2]), "+f"((d)[3]) \
                 : "r"((a)[0]), "r"((a)[1]), "r"((a)[2]), "r"((a)[3]), \
                   "r"((b)[0]), "r"((b)[1]))

__device__ __forceinline__ void split_bf(float x, unsigned short& h, unsigned short& l) {
    __nv_bfloat16 hb = __float2bfloat16_rn(x);
    float r = x - __bfloat162float(hb);
    __nv_bfloat16 lb = __float2bfloat16_rn(r);
    h = __bfloat16_as_ushort(hb);
    l = __bfloat16_as_ushort(lb);
}

// smem tile: [128 rows][32 bf16], rows padded to 80B (conflict-free: 20r mod 32
// spans all banks, no XOR swizzle needed).
#define TSZ         10240                 // 128 * 80
#define STAGE_BYTES (4 * TSZ)             // Ah, Al, Bh, Bl = 40960
#define NSTAGE      4
#define SMEM_TOTAL  (NSTAGE * STAGE_BYTES)   // 163840

// ---------------------------------------------------------------------------
// Split-bf16 mma.sync GEMM.  Block tile 128x128, 512 threads (16 warps,
// warp tile 32x32, 4 warps/SMSP), K chunks of 32, 4-stage cp.async.
//   CFG 0 (proj):   z selects q/k/v. A = fp32 input (split in staging),
//                   B = g_wh/g_wl[z]. K=256. Epilogue: +bias ->
//                   z<2: split to g_qh/g_ql | g_kh/g_kl;
//                   z=2: transpose via smem -> g_vth/g_vtl [b][d][sq].
//   CFG 1 (scores): A=q, B=k (batch z), K=256, fp32 -> g_S[z].
//   CFG 2 (ctx):    A = P hi/lo rows in g_S (ld 8192, lo at +4096),
//                   B = vt, K=4096, fp32 -> out.
// ---------------------------------------------------------------------------
template<int CFG>
__global__ __launch_bounds__(512, 1)
void gemm_kernel(const float* __restrict__ in_q, const float* __restrict__ in_k,
                 const float* __restrict__ in_v,
                 const float* __restrict__ bq, const float* __restrict__ bk,
                 const float* __restrict__ bv, float* __restrict__ out)
{
    constexpr int K  = (CFG == 2) ? 4096 : 256;
    constexpr int NC = K / 32;
    constexpr long long LDA = (CFG == 2) ? 8192 : 256;
    constexpr long long LDB = (CFG == 2) ? 4096 : 256;

    extern __shared__ __align__(128) char sm[];
    const uint32_t smb = smem_u32(sm);
    const int tid = threadIdx.x;
    const int w = tid >> 5, lane = tid & 31;
    const int wm = w & 3, wn = w >> 2;
    const int m0 = blockIdx.x * 128, n0 = blockIdx.y * 128;
    const int z = blockIdx.z;

    const float* Afp = nullptr;
    const unsigned short *sp0 = nullptr, *sp1 = nullptr, *sp2 = nullptr, *sp3 = nullptr;
    if (CFG == 0) {
        Afp = (z == 0 ? in_q : z == 1 ? in_k : in_v) + (long long)m0 * 256;
        sp2 = g_wh[z] + n0 * 256;
        sp3 = g_wl[z] + n0 * 256;
    } else if (CFG == 1) {
        long long b = z;
        sp0 = g_qh + (b * SEQ + m0) * 256;
        sp1 = g_ql + (b * SEQ + m0) * 256;
        sp2 = g_kh + (b * SEQ + n0) * 256;
        sp3 = g_kl + (b * SEQ + n0) * 256;
    } else {
        long long b = z;
        sp0 = reinterpret_cast<const unsigned short*>(g_S)
              + b * SEQ * 8192 + (long long)m0 * 8192;
        sp1 = sp0 + 4096;
        sp2 = g_vth + b * (long long)DIM * SEQ + (long long)n0 * 4096;
        sp3 = g_vtl + b * (long long)DIM * SEQ + (long long)n0 * 4096;
    }

    float acc[2][4][4] = {};

    auto stage = [&](int c) {
        const int buf = c & 3;
        const uint32_t sb = smb + buf * STAGE_BYTES;
        char* sbp = sm + buf * STAGE_BYTES;
        const int k0 = c * 32;
        if (CFG == 0) {
            // A fp32 -> hi/lo bf16 split in registers, STS
#pragma unroll
            for (int i = tid; i < 1024; i += 512) {
                int r = i >> 3, kq = (i & 7) * 4;
                float4 v = *reinterpret_cast<const float4*>(Afp + r * 256 + k0 + kq);
                ushort4 hh, ll;
                split_bf(v.x, hh.x, ll.x); split_bf(v.y, hh.y, ll.y);
                split_bf(v.z, hh.z, ll.z); split_bf(v.w, hh.w, ll.w);
                int off = r * 80 + kq * 2;
                *reinterpret_cast<ushort4*>(sbp + off)       = hh;
                *reinterpret_cast<ushort4*>(sbp + TSZ + off) = ll;
            }
            // B hi/lo via cp.async
#pragma unroll
            for (int i = tid; i < 1024; i += 512) {
                int sp = i >> 9, r = (i >> 2) & 127, kc = (i & 3) * 8;
                const unsigned short* src = (sp ? sp3 : sp2) + r * 256 + k0 + kc;
                CP16(sb + (2 + sp) * TSZ + r * 80 + kc * 2, src);
            }
        } else {
#pragma unroll
            for (int i = tid; i < 2048; i += 512) {
                int sp = i >> 9, r = (i >> 2) & 127, kc = (i & 3) * 8;
                const unsigned short* base =
                    (sp == 0 ? sp0 : sp == 1 ? sp1 : sp == 2 ? sp2 : sp3);
                const unsigned short* src = base + (long long)r * (sp < 2 ? LDA : LDB)
                                            + k0 + kc;
                CP16(sb + sp * TSZ + r * 80 + kc * 2, src);
            }
        }
        CP_COMMIT();
    };

    // ldmatrix per-thread constants
    const int a_r0 = wm * 32 + (lane & 7) + ((lane >> 3) & 1) * 8;   // + mt*16
    const int a_kb = (lane >> 4) * 16;
    const int b_n0 = wn * 32 + (lane & 7) + (lane >> 4) * 8;          // + g*16
    const int b_kb = ((lane >> 3) & 1) * 16;

    auto compute = [&](int buf) {
        const uint32_t sb = smb + buf * STAGE_BYTES;
#pragma unroll
        for (int ks = 0; ks < 2; ks++) {
            uint32_t Ahf[2][4], Alf[2][4], Bhf[2][4], Blf[2][4];
#pragma unroll
            for (int mt = 0; mt < 2; mt++) {
                int row = a_r0 + mt * 16;
                uint32_t ad = sb + row * 80 + ks * 32 + a_kb;
                LDSM4(Ahf[mt], ad);
                LDSM4(Alf[mt], ad + TSZ);
            }
#pragma unroll
            for (int g = 0; g < 2; g++) {
                int nrow = b_n0 + g * 16;
                uint32_t bd = sb + 2 * TSZ + nrow * 80 + ks * 32 + b_kb;
                LDSM4(Bhf[g], bd);
                LDSM4(Blf[g], bd + TSZ);
            }
#pragma unroll
            for (int mt = 0; mt < 2; mt++)
#pragma unroll
                for (int g = 0; g < 2; g++)
#pragma unroll
                    for (int sub = 0; sub < 2; sub++) {
                        int nt = g * 2 + sub;
                        MMA(acc[mt][nt], Ahf[mt], Bhf[g] + sub * 2);   // hi*hi
                        MMA(acc[mt][nt], Ahf[mt], Blf[g] + sub * 2);   // hi*lo
                        MMA(acc[mt][nt], Alf[mt], Bhf[g] + sub * 2);   // lo*hi
                    }
        }
    };

    stage(0); stage(1); stage(2);
    for (int c = 0; c < NC; c++) {
        if (c + 3 <= NC) CP_WAIT2();
        else if (c + 2 == NC) CP_WAIT1();
        else CP_WAIT0();
        __syncthreads();
        if (c + 3 < NC) stage(c + 3);
        compute(c & 3);
    }
    __syncthreads();

    // ---------------- epilogue ----------------
    if (CFG == 0) {
        const float* bias = (z == 0) ? bq : (z == 1) ? bk : bv;
        if (z < 2) {
            unsigned short* DH = (z == 0) ? g_qh : g_kh;
            unsigned short* DL = (z == 0) ? g_ql : g_kl;
#pragma unroll
            for (int mt = 0; mt < 2; mt++)
#pragma unroll
                for (int nt = 0; nt < 4; nt++) {
                    int m  = m0 + wm * 32 + mt * 16 + (lane >> 2);
                    int ng = n0 + wn * 32 + nt * 8 + (lane & 3) * 2;
                    float b0 = bias[ng], b1 = bias[ng + 1];
                    float* a = acc[mt][nt];
                    ushort2 h2, l2;
                    split_bf(a[0] + b0, h2.x, l2.x); split_bf(a[1] + b1, h2.y, l2.y);
                    *reinterpret_cast<ushort2*>(&DH[(long long)m * 256 + ng]) = h2;
                    *reinterpret_cast<ushort2*>(&DL[(long long)m * 256 + ng]) = l2;
                    split_bf(a[2] + b0, h2.x, l2.x); split_bf(a[3] + b1, h2.y, l2.y);
                    *reinterpret_cast<ushort2*>(&DH[(long long)(m + 8) * 256 + ng]) = h2;
                    *reinterpret_cast<ushort2*>(&DL[(long long)(m + 8) * 256 + ng]) = l2;
                }
        } else {
            // V: transpose through smem, split-store to g_vth/g_vtl [b][d][sq]
            float* Cs = reinterpret_cast<float*>(sm);      // [128][132]
#pragma unroll
            for (int mt = 0; mt < 2; mt++)
#pragma unroll
                for (int nt = 0; nt < 4; nt++) {
                    int ml = wm * 32 + mt * 16 + (lane >> 2);
                    int nl = wn * 32 + nt * 8 + (lane & 3) * 2;
                    float b0 = bias[n0 + nl], b1 = bias[n0 + nl + 1];
                    float* a = acc[mt][nt];
                    *reinterpret_cast<float2*>(&Cs[ml * 132 + nl])
                        = make_float2(a[0] + b0, a[1] + b1);
                    *reinterpret_cast<float2*>(&Cs[(ml + 8) * 132 + nl])
                        = make_float2(a[2] + b0, a[3] + b1);
                }
            __syncthreads();
            int nl = tid & 127, part = tid >> 7;        // 4 parts x 32 sq
            long long bb = m0 >> 12;
            int sq0 = (m0 & 4095) + part * 32;
            long long obase = bb * (long long)DIM * SEQ
                            + (long long)(n0 + nl) * SEQ + sq0;
#pragma unroll
            for (int j = 0; j < 8; j++) {
                int ml = part * 32 + j * 4;
                ushort4 hh, ll;
                split_bf(Cs[(ml + 0) * 132 + nl], hh.x, ll.x);
                split_bf(Cs[(ml + 1) * 132 + nl], hh.y, ll.y);
                split_bf(Cs[(ml + 2) * 132 + nl], hh.z, ll.z);
                split_bf(Cs[(ml + 3) * 132 + nl], hh.w, ll.w);
                *reinterpret_cast<ushort4*>(&g_vth[obase + j * 4]) = hh;
                *reinterpret_cast<ushort4*>(&g_vtl[obase + j * 4]) = ll;
            }
        }
    } else if (CFG == 1) {
        long long base = (long long)z * SEQ * SEQ;
#pragma unroll
        for (int mt = 0; mt < 2; mt++)
#pragma unroll
            for (int nt = 0; nt < 4; nt++) {
                int m = m0 + wm * 32 + mt * 16 + (lane >> 2);
                int n = n0 + wn * 32 + nt * 8 + (lane & 3) * 2;
                float* a = acc[mt][nt];
                *reinterpret_cast<float2*>(&g_S[base + (long long)m * 4096 + n])
                    = make_float2(a[0], a[1]);
                *reinterpret_cast<float2*>(&g_S[base + (long long)(m + 8) * 4096 + n])
                    = make_float2(a[2], a[3]);
            }
    } else {
#pragma unroll
        for (int mt = 0; mt < 2; mt++)
#pragma unroll
            for (int nt = 0; nt < 4; nt++) {
                int m = m0 + wm * 32 + mt * 16 + (lane >> 2);
                int n = n0 + wn * 32 + nt * 8 + (lane & 3) * 2;
                float* a = acc[mt][nt];
                long long rb = ((long long)z * SEQ + m) * 256 + n;
                *reinterpret_cast<float2*>(&out[rb])        = make_float2(a[0], a[1]);
                *reinterpret_cast<float2*>(&out[rb + 2048]) = make_float2(a[2], a[3]);
            }
    }
}

// ---------------------------------------------------------------------------
// merged weight split: Wq/Wk/Wv -> g_wh/g_wl
// ---------------------------------------------------------------------------
__global__ __launch_bounds__(256) void split_w_kernel(
    const float* __restrict__ Wq, const float* __restrict__ Wk,
    const float* __restrict__ Wv)
{
    int gi = blockIdx.x * 256 + threadIdx.x;   // 0..49151 (3 * 16384 float4)
    int wsel = gi >> 14;
    int i = gi & 16383;
    const float* x = (wsel == 0) ? Wq : (wsel == 1) ? Wk : Wv;
    float4 v = reinterpret_cast<const float4*>(x)[i];
    ushort4 hh, ll;
    split_bf(v.x, hh.x, ll.x);
    split_bf(v.y, hh.y, ll.y);
    split_bf(v.z, hh.z, ll.z);
    split_bf(v.w, hh.w, ll.w);
    reinterpret_cast<ushort4*>(g_wh[wsel])[i] = hh;
    reinterpret_cast<ushort4*>(g_wl[wsel])[i] = ll;
}

// ---------------------------------------------------------------------------
// softmax over rows of 4096 in g_S, IN PLACE: fp32 row -> hi bf16 (first
// 8KB) + lo bf16 (second 8KB) of normalized P.
// ---------------------------------------------------------------------------
__global__ __launch_bounds__(256, 1) void softmax_kernel()
{
    __shared__ float red[8];
    const int tid = threadIdx.x;
    const int w = tid >> 5, lane = tid & 31;
    float* S = g_S + (long long)blockIdx.x * 4096;

    float4 x[4];
#pragma unroll
    for (int j = 0; j < 4; j++)
        x[j] = *reinterpret_cast<const float4*>(S + (j * 256 + tid) * 4);

    float mx = -1e30f;
#pragma unroll
    for (int j = 0; j < 4; j++)
        mx = fmaxf(mx, fmaxf(fmaxf(x[j].x, x[j].y), fmaxf(x[j].z, x[j].w)));
#pragma unroll
    for (int o = 16; o; o >>= 1) mx = fmaxf(mx, __shfl_xor_sync(~0u, mx, o));
    if (lane == 0) red[w] = mx;
    __syncthreads();
    mx = red[0];
#pragma unroll
    for (int i = 1; i < 8; i++) mx = fmaxf(mx, red[i]);
    __syncthreads();

    float p[16];
    float sum = 0.f;
#pragma unroll
    for (int j = 0; j < 4; j++) {
        p[4 * j + 0] = __expf(x[j].x - mx);
        p[4 * j + 1] = __expf(x[j].y - mx);
        p[4 * j + 2] = __expf(x[j].z - mx);
        p[4 * j + 3] = __expf(x[j].w - mx);
        sum += (p[4 * j] + p[4 * j + 1]) + (p[4 * j + 2] + p[4 * j + 3]);
    }
#pragma unroll
    for (int o = 16; o; o >>= 1) sum += __shfl_xor_sync(~0u, sum, o);
    if (lane == 0) red[w] = sum;
    __syncthreads();
    sum = 0.f;
#pragma unroll
    for (int i = 0; i < 8; i++) sum += red[i];
    float inv = 1.f / sum;
    __syncthreads();   // all reads done; safe to overwrite row

    unsigned short* Ph = reinterpret_cast<unsigned short*>(S);
    unsigned short* Pl = Ph + 4096;
#pragma unroll
    for (int j = 0; j < 4; j++) {
        ushort4 hh, ll;
        split_bf(p[4 * j + 0] * inv, hh.x, ll.x);
        split_bf(p[4 * j + 1] * inv, hh.y, ll.y);
        split_bf(p[4 * j + 2] * inv, hh.z, ll.z);
        split_bf(p[4 * j + 3] * inv, hh.w, ll.w);
        int o = (j * 256 + tid) * 4;
        *reinterpret_cast<ushort4*>(Ph + o) = hh;
        *reinterpret_cast<ushort4*>(Pl + o) = ll;
    }
}

// ---------------------------------------------------------------------------
extern "C" void kernel_launch(void* const* d_in, const int* in_sizes, int n_in,
                              void* d_out, int out_size)
{
    (void)in_sizes; (void)n_in; (void)out_size;
    const float* query  = (const float*)d_in[0];
    const float* keys   = (const float*)d_in[1];
    const float* values = (const float*)d_in[2];
    const float* Wq     = (const float*)d_in[3];
    const float* bq     = (const float*)d_in[4];
    const float* Wk     = (const float*)d_in[5];
    const float* bk     = (const float*)d_in[6];
    const float* Wv     = (const float*)d_in[7];
    const float* bv     = (const float*)d_in[8];
    float* out = (float*)d_out;

    cudaFuncSetAttribute(gemm_kernel<0>, cudaFuncAttributeMaxDynamicSharedMemorySize, SMEM_TOTAL);
    cudaFuncSetAttribute(gemm_kernel<1>, cudaFuncAttributeMaxDynamicSharedMemorySize, SMEM_TOTAL);
    cudaFuncSetAttribute(gemm_kernel<2>, cudaFuncAttributeMaxDynamicSharedMemorySize, SMEM_TOTAL);

    // 1) weight splits (one launch)
    split_w_kernel<<<192, 256>>>(Wq, Wk, Wv);

    // 2) all three projections (one launch; z selects q/k/v)
    gemm_kernel<0><<<dim3(NTOK / 128, 2, 3), 512, SMEM_TOTAL>>>(
        query, keys, values, bq, bk, bv, nullptr);

    // 3) scores, all batches
    gemm_kernel<1><<<dim3(SEQ / 128, SEQ / 128, NBATCH), 512, SMEM_TOTAL>>>(
        nullptr, nullptr, nullptr, nullptr, nullptr, nullptr, nullptr);

    // 4) softmax, in place
    softmax_kernel<<<NTOK, 256>>>();

    // 5) context
    gemm_kernel<2><<<dim3(SEQ / 128, 2, NBATCH), 512, SMEM_TOTAL>>>(
        nullptr, nullptr, nullptr, nullptr, nullptr, nullptr, out);
}

// round 7
// speedup vs baseline: 1.2746x; 1.2746x over previous
#include <cuda_runtime.h>
#include <cuda_bf16.h>
#include <stdint.h>

#define NBATCH 8
#define SEQ    4096
#define DIM    256
#define NTOK   (NBATCH * SEQ)                 // 32768
#define PROJ_ELEMS (NTOK * DIM)               // 8388608
#define S_ELEMS ((long long)NBATCH * SEQ * SEQ)

// ---------------- scratch (static device arrays) ---------------------------
// g_S: fp32 scores; softmax overwrites each 4096-float row in place with
// 4096 hi-bf16 + 4096 lo-bf16 of normalized P.
__device__ __align__(16) float          g_S[S_ELEMS];                 // 537 MB
__device__ __align__(16) unsigned short g_wh[3][DIM * DIM];
__device__ __align__(16) unsigned short g_wl[3][DIM * DIM];
__device__ __align__(16) unsigned short g_qh[PROJ_ELEMS], g_ql[PROJ_ELEMS];
__device__ __align__(16) unsigned short g_kh[PROJ_ELEMS], g_kl[PROJ_ELEMS];
__device__ __align__(16) unsigned short g_vth[PROJ_ELEMS], g_vtl[PROJ_ELEMS];

// ---------------- helpers ---------------------------------------------------
__device__ __forceinline__ uint32_t smem_u32(const void* p) {
    uint32_t a;
    asm("{ .reg .u64 t; cvta.to.shared.u64 t, %1; cvt.u32.u64 %0, t; }"
        : "=r"(a) : "l"(p));
    return a;
}

#define CP16(dst, src) \
    asm volatile("cp.async.cg.shared.global [%0], [%1], 16;" \
                 :: "r"(dst), "l"(src) : "memory")
#define CP_COMMIT()  asm volatile("cp.async.commit_group;" ::: "memory")
#define CP_WAIT1()   asm volatile("cp.async.wait_group 1;" ::: "memory")
#define CP_WAIT0()   asm volatile("cp.async.wait_group 0;" ::: "memory")

#define LDSM4(r, addr) \
    asm volatile("ldmatrix.sync.aligned.m8n8.x4.shared.b16 {%0,%1,%2,%3}, [%4];" \
                 : "=r"((r)[0]), "=r"((r)[1]), "=r"((r)[2]), "=r"((r)[3]) \
                 : "r"(addr))

#define MMA(d, a, b) \
    asm volatile("mma.sync.aligned.m16n8k16.row.col.f32.bf16.bf16.f32 " \
                 "{%0,%1,%2,%3},{%4,%5,%6,%7},{%8,%9},{%0,%1,%2,%3};" \
                 : "+f"((d)[0]), "+f"((d)[1]), "+f"((d)[2]), "+f"((d)[3]) \
                 : "r"((a)[0]), "r"((a)[1]), "r"((a)[2]), "r"((a)[3]), \
                   "r"((b)[0]), "r"((b)[1]))

__device__ __forceinline__ void split_bf(float x, unsigned short& h, unsigned short& l) {
    __nv_bfloat16 hb = __float2bfloat16_rn(x);
    float r = x - __bfloat162float(hb);
    __nv_bfloat16 lb = __float2bfloat16_rn(r);
    h = __bfloat16_as_ushort(hb);
    l = __bfloat16_as_ushort(lb);
}

// smem: per-stage A (2 splits x 128 rows x 64 bf16 = 128B rows, XOR-swizzled)
//       and B (2 splits x 256 rows x 64 bf16).
#define A_SP        16384                 // 128 * 128B
#define B_SP        32768                 // 256 * 128B
#define STAGE_BYTES (2 * A_SP + 2 * B_SP) // 98304
#define SMEM_TOTAL  (2 * STAGE_BYTES)     // 196608
#define SWB(kbyte, r) ((kbyte) ^ (((r) & 7) << 4))

// ---------------------------------------------------------------------------
// Split-bf16 mma.sync GEMM. Block tile 128x256, 256 threads (8 warps, 2x4,
// warp tile 64x64), K chunks of 64, 2-stage cp.async double buffer.
// 3 MMAs per product (hi*hi + hi*lo + lo*hi), fp32 accumulate.
//   CFG 0 (proj):   z selects q/k/v. A = fp32 input (split in staging),
//                   B = g_wh/g_wl[z], K=256, N=256 in one tile. Epilogue:
//                   +bias -> z<2: split to g_qh/g_ql | g_kh/g_kl;
//                   z=2: transpose via smem -> g_vth/g_vtl [b][d][sq].
//   CFG 1 (scores): A=q, B=k (batch z), K=256, fp32 -> g_S[z].
//   CFG 2 (ctx):    A = P hi/lo rows in g_S (ld 8192, lo at +4096),
//                   B = vt, K=4096, fp32 -> out. N=256 in one tile.
// ---------------------------------------------------------------------------
template<int CFG>
__global__ __launch_bounds__(256, 1)
void gemm_kernel(const float* __restrict__ in_q, const float* __restrict__ in_k,
                 const float* __restrict__ in_v,
                 const float* __restrict__ bq, const float* __restrict__ bk,
                 const float* __restrict__ bv, float* __restrict__ out)
{
    constexpr int K  = (CFG == 2) ? 4096 : 256;
    constexpr int NC = K / 64;
    constexpr long long LDA = (CFG == 2) ? 8192 : 256;
    constexpr long long LDB = (CFG == 2) ? 4096 : 256;

    extern __shared__ __align__(128) char sm[];
    const uint32_t smb = smem_u32(sm);
    const int tid = threadIdx.x;
    const int w = tid >> 5, lane = tid & 31;
    const int wm = w & 1, wn = w >> 1;          // 2 x 4 warp grid
    const int m0 = blockIdx.x * 128, n0 = blockIdx.y * 256;
    const int z = blockIdx.z;

    const float* Afp = nullptr;
    const unsigned short *sp0 = nullptr, *sp1 = nullptr, *sp2 = nullptr, *sp3 = nullptr;
    if (CFG == 0) {
        Afp = (z == 0 ? in_q : z == 1 ? in_k : in_v) + (long long)m0 * 256;
        sp2 = g_wh[z];
        sp3 = g_wl[z];
    } else if (CFG == 1) {
        long long b = z;
        sp0 = g_qh + (b * SEQ + m0) * 256;
        sp1 = g_ql + (b * SEQ + m0) * 256;
        sp2 = g_kh + (b * SEQ + n0) * 256;
        sp3 = g_kl + (b * SEQ + n0) * 256;
    } else {
        long long b = z;
        sp0 = reinterpret_cast<const unsigned short*>(g_S)
              + b * SEQ * 8192 + (long long)m0 * 8192;
        sp1 = sp0 + 4096;
        sp2 = g_vth + b * (long long)DIM * SEQ;
        sp3 = g_vtl + b * (long long)DIM * SEQ;
    }

    float acc[4][8][4] = {};    // [mt 16-rows][nt 8-cols][frag]

    auto stage = [&](int c) {
        const int buf = c & 1;
        const uint32_t sb = smb + buf * STAGE_BYTES;
        char* sbp = sm + buf * STAGE_BYTES;
        const int k0 = c * 64;
        if (CFG == 0) {
            // A fp32 -> hi/lo bf16 split in registers, STS
#pragma unroll
            for (int t = tid; t < 2048; t += 256) {
                int r = t >> 4, kq = (t & 15) * 4;       // 128 rows x 16 float4
                float4 v = *reinterpret_cast<const float4*>(Afp + r * 256 + k0 + kq);
                ushort4 hh, ll;
                split_bf(v.x, hh.x, ll.x); split_bf(v.y, hh.y, ll.y);
                split_bf(v.z, hh.z, ll.z); split_bf(v.w, hh.w, ll.w);
                int off = r * 128 + SWB(kq * 2, r);
                *reinterpret_cast<ushort4*>(sbp + off)        = hh;
                *reinterpret_cast<ushort4*>(sbp + A_SP + off) = ll;
            }
        } else {
#pragma unroll
            for (int t = tid; t < 2048; t += 256) {
                int sp = t >> 10, r = (t >> 3) & 127, kc = (t & 7) * 8;
                const unsigned short* src = (sp ? sp1 : sp0) + (long long)r * LDA + k0 + kc;
                CP16(sb + sp * A_SP + r * 128 + SWB(kc * 2, r), src);
            }
        }
#pragma unroll
        for (int t = tid; t < 4096; t += 256) {
            int sp = t >> 11, r = (t >> 3) & 255, kc = (t & 7) * 8;
            const unsigned short* src = (sp ? sp3 : sp2) + (long long)r * LDB + k0 + kc;
            CP16(sb + 2 * A_SP + sp * B_SP + r * 128 + SWB(kc * 2, r), src);
        }
        CP_COMMIT();
    };

    // ldmatrix per-thread constants
    const int a_r0 = wm * 64 + (lane & 7) + ((lane >> 3) & 1) * 8;   // + mt*16
    const int a_kb = (lane >> 4) * 16;
    const int b_n0 = wn * 64 + (lane & 7) + (lane >> 4) * 8;          // + g*16
    const int b_kb = ((lane >> 3) & 1) * 16;

    auto compute = [&](int buf) {
        const uint32_t sa = smb + buf * STAGE_BYTES;
        const uint32_t sbb = sa + 2 * A_SP;
#pragma unroll
        for (int ks = 0; ks < 4; ks++) {
            uint32_t Ahf[4][4], Alf[4][4];
#pragma unroll
            for (int mt = 0; mt < 4; mt++) {
                int row = a_r0 + mt * 16;
                uint32_t ad = sa + row * 128 + SWB(ks * 32 + a_kb, row);
                LDSM4(Ahf[mt], ad);
                LDSM4(Alf[mt], ad + A_SP);
            }
#pragma unroll
            for (int g = 0; g < 4; g++) {
                int nrow = b_n0 + g * 16;
                uint32_t bd = sbb + nrow * 128 + SWB(ks * 32 + b_kb, nrow);
                uint32_t Bh[4], Bl[4];
                LDSM4(Bh, bd);
                LDSM4(Bl, bd + B_SP);
#pragma unroll
                for (int mt = 0; mt < 4; mt++)
#pragma unroll
                    for (int sub = 0; sub < 2; sub++) {
                        int nt = g * 2 + sub;
                        MMA(acc[mt][nt], Ahf[mt], Bh + sub * 2);   // hi*hi
                        MMA(acc[mt][nt], Ahf[mt], Bl + sub * 2);   // hi*lo
                        MMA(acc[mt][nt], Alf[mt], Bh + sub * 2);   // lo*hi
                    }
            }
        }
    };

    stage(0);
    for (int c = 0; c < NC; c++) {
        __syncthreads();                 // prior compute done before buffer reuse
        if (c + 1 < NC) stage(c + 1);
        if (c + 1 < NC) CP_WAIT1(); else CP_WAIT0();
        __syncthreads();
        compute(c & 1);
    }
    __syncthreads();

    // ---------------- epilogue ----------------
    if (CFG == 0) {
        const float* bias = (z == 0) ? bq : (z == 1) ? bk : bv;
        if (z < 2) {
            unsigned short* DH = (z == 0) ? g_qh : g_kh;
            unsigned short* DL = (z == 0) ? g_ql : g_kl;
#pragma unroll
            for (int mt = 0; mt < 4; mt++)
#pragma unroll
                for (int nt = 0; nt < 8; nt++) {
                    int m  = m0 + wm * 64 + mt * 16 + (lane >> 2);
                    int ng = wn * 64 + nt * 8 + (lane & 3) * 2;
                    float b0 = bias[ng], b1 = bias[ng + 1];
                    float* a = acc[mt][nt];
                    ushort2 h2, l2;
                    split_bf(a[0] + b0, h2.x, l2.x); split_bf(a[1] + b1, h2.y, l2.y);
                    *reinterpret_cast<ushort2*>(&DH[(long long)m * 256 + ng]) = h2;
                    *reinterpret_cast<ushort2*>(&DL[(long long)m * 256 + ng]) = l2;
                    split_bf(a[2] + b0, h2.x, l2.x); split_bf(a[3] + b1, h2.y, l2.y);
                    *reinterpret_cast<ushort2*>(&DH[(long long)(m + 8) * 256 + ng]) = h2;
                    *reinterpret_cast<ushort2*>(&DL[(long long)(m + 8) * 256 + ng]) = l2;
                }
        } else {
            // V: transpose through smem -> g_vth/g_vtl [b][d][sq]
            float* Cs = reinterpret_cast<float*>(sm);      // [128][260]
#pragma unroll
            for (int mt = 0; mt < 4; mt++)
#pragma unroll
                for (int nt = 0; nt < 8; nt++) {
                    int ml = wm * 64 + mt * 16 + (lane >> 2);
                    int nl = wn * 64 + nt * 8 + (lane & 3) * 2;
                    float b0 = bias[nl], b1 = bias[nl + 1];
                    float* a = acc[mt][nt];
                    *reinterpret_cast<float2*>(&Cs[ml * 260 + nl])
                        = make_float2(a[0] + b0, a[1] + b1);
                    *reinterpret_cast<float2*>(&Cs[(ml + 8) * 260 + nl])
                        = make_float2(a[2] + b0, a[3] + b1);
                }
            __syncthreads();
            int nl = tid;                                  // one d-column per thread
            long long bb = m0 >> 12;
            int sq0 = m0 & 4095;
            long long obase = bb * (long long)DIM * SEQ + (long long)nl * SEQ + sq0;
#pragma unroll
            for (int j = 0; j < 32; j++) {
                int ml = j * 4;
                ushort4 hh, ll;
                split_bf(Cs[(ml + 0) * 260 + nl], hh.x, ll.x);
                split_bf(Cs[(ml + 1) * 260 + nl], hh.y, ll.y);
                split_bf(Cs[(ml + 2) * 260 + nl], hh.z, ll.z);
                split_bf(Cs[(ml + 3) * 260 + nl], hh.w, ll.w);
                *reinterpret_cast<ushort4*>(&g_vth[obase + ml]) = hh;
                *reinterpret_cast<ushort4*>(&g_vtl[obase + ml]) = ll;
            }
        }
    } else if (CFG == 1) {
        long long base = (long long)z * SEQ * SEQ;
#pragma unroll
        for (int mt = 0; mt < 4; mt++)
#pragma unroll
            for (int nt = 0; nt < 8; nt++) {
                int m = m0 + wm * 64 + mt * 16 + (lane >> 2);
                int n = n0 + wn * 64 + nt * 8 + (lane & 3) * 2;
                float* a = acc[mt][nt];
                *reinterpret_cast<float2*>(&g_S[base + (long long)m * 4096 + n])
                    = make_float2(a[0], a[1]);
                *reinterpret_cast<float2*>(&g_S[base + (long long)(m + 8) * 4096 + n])
                    = make_float2(a[2], a[3]);
            }
    } else {
#pragma unroll
        for (int mt = 0; mt < 4; mt++)
#pragma unroll
            for (int nt = 0; nt < 8; nt++) {
                int m = m0 + wm * 64 + mt * 16 + (lane >> 2);
                int n = wn * 64 + nt * 8 + (lane & 3) * 2;
                float* a = acc[mt][nt];
                long long rb = ((long long)z * SEQ + m) * 256 + n;
                *reinterpret_cast<float2*>(&out[rb])        = make_float2(a[0], a[1]);
                *reinterpret_cast<float2*>(&out[rb + 2048]) = make_float2(a[2], a[3]);
            }
    }
}

// ---------------------------------------------------------------------------
// merged weight split: Wq/Wk/Wv -> g_wh/g_wl
// ---------------------------------------------------------------------------
__global__ __launch_bounds__(256) void split_w_kernel(
    const float* __restrict__ Wq, const float* __restrict__ Wk,
    const float* __restrict__ Wv)
{
    int gi = blockIdx.x * 256 + threadIdx.x;   // 0..49151 (3 * 16384 float4)
    int wsel = gi >> 14;
    int i = gi & 16383;
    const float* x = (wsel == 0) ? Wq : (wsel == 1) ? Wk : Wv;
    float4 v = reinterpret_cast<const float4*>(x)[i];
    ushort4 hh, ll;
    split_bf(v.x, hh.x, ll.x);
    split_bf(v.y, hh.y, ll.y);
    split_bf(v.z, hh.z, ll.z);
    split_bf(v.w, hh.w, ll.w);
    reinterpret_cast<ushort4*>(g_wh[wsel])[i] = hh;
    reinterpret_cast<ushort4*>(g_wl[wsel])[i] = ll;
}

// ---------------------------------------------------------------------------
// softmax over rows of 4096 in g_S, IN PLACE: fp32 row -> hi bf16 (first
// 8KB) + lo bf16 (second 8KB) of normalized P.  (82% HBM roofline already.)
// ---------------------------------------------------------------------------
__global__ __launch_bounds__(256, 1) void softmax_kernel()
{
    __shared__ float red[8];
    const int tid = threadIdx.x;
    const int w = tid >> 5, lane = tid & 31;
    float* S = g_S + (long long)blockIdx.x * 4096;

    float4 x[4];
#pragma unroll
    for (int j = 0; j < 4; j++)
        x[j] = *reinterpret_cast<const float4*>(S + (j * 256 + tid) * 4);

    float mx = -1e30f;
#pragma unroll
    for (int j = 0; j < 4; j++)
        mx = fmaxf(mx, fmaxf(fmaxf(x[j].x, x[j].y), fmaxf(x[j].z, x[j].w)));
#pragma unroll
    for (int o = 16; o; o >>= 1) mx = fmaxf(mx, __shfl_xor_sync(~0u, mx, o));
    if (lane == 0) red[w] = mx;
    __syncthreads();
    mx = red[0];
#pragma unroll
    for (int i = 1; i < 8; i++) mx = fmaxf(mx, red[i]);
    __syncthreads();

    float p[16];
    float sum = 0.f;
#pragma unroll
    for (int j = 0; j < 4; j++) {
        p[4 * j + 0] = __expf(x[j].x - mx);
        p[4 * j + 1] = __expf(x[j].y - mx);
        p[4 * j + 2] = __expf(x[j].z - mx);
        p[4 * j + 3] = __expf(x[j].w - mx);
        sum += (p[4 * j] + p[4 * j + 1]) + (p[4 * j + 2] + p[4 * j + 3]);
    }
#pragma unroll
    for (int o = 16; o; o >>= 1) sum += __shfl_xor_sync(~0u, sum, o);
    if (lane == 0) red[w] = sum;
    __syncthreads();
    sum = 0.f;
#pragma unroll
    for (int i = 0; i < 8; i++) sum += red[i];
    float inv = 1.f / sum;
    __syncthreads();   // all reads done; safe to overwrite row

    unsigned short* Ph = reinterpret_cast<unsigned short*>(S);
    unsigned short* Pl = Ph + 4096;
#pragma unroll
    for (int j = 0; j < 4; j++) {
        ushort4 hh, ll;
        split_bf(p[4 * j + 0] * inv, hh.x, ll.x);
        split_bf(p[4 * j + 1] * inv, hh.y, ll.y);
        split_bf(p[4 * j + 2] * inv, hh.z, ll.z);
        split_bf(p[4 * j + 3] * inv, hh.w, ll.w);
        int o = (j * 256 + tid) * 4;
        *reinterpret_cast<ushort4*>(Ph + o) = hh;
        *reinterpret_cast<ushort4*>(Pl + o) = ll;
    }
}

// ---------------------------------------------------------------------------
extern "C" void kernel_launch(void* const* d_in, const int* in_sizes, int n_in,
                              void* d_out, int out_size)
{
    (void)in_sizes; (void)n_in; (void)out_size;
    const float* query  = (const float*)d_in[0];
    const float* keys   = (const float*)d_in[1];
    const float* values = (const float*)d_in[2];
    const float* Wq     = (const float*)d_in[3];
    const float* bq     = (const float*)d_in[4];
    const float* Wk     = (const float*)d_in[5];
    const float* bk     = (const float*)d_in[6];
    const float* Wv     = (const float*)d_in[7];
    const float* bv     = (const float*)d_in[8];
    float* out = (float*)d_out;

    cudaFuncSetAttribute(gemm_kernel<0>, cudaFuncAttributeMaxDynamicSharedMemorySize, SMEM_TOTAL);
    cudaFuncSetAttribute(gemm_kernel<1>, cudaFuncAttributeMaxDynamicSharedMemorySize, SMEM_TOTAL);
    cudaFuncSetAttribute(gemm_kernel<2>, cudaFuncAttributeMaxDynamicSharedMemorySize, SMEM_TOTAL);

    // 1) weight splits (one launch)
    split_w_kernel<<<192, 256>>>(Wq, Wk, Wv);

    // 2) all three projections (one launch; z selects q/k/v), N=256 per tile
    gemm_kernel<0><<<dim3(NTOK / 128, 1, 3), 256, SMEM_TOTAL>>>(
        query, keys, values, bq, bk, bv, nullptr);

    // 3) scores, all batches
    gemm_kernel<1><<<dim3(SEQ / 128, SEQ / 256, NBATCH), 256, SMEM_TOTAL>>>(
        nullptr, nullptr, nullptr, nullptr, nullptr, nullptr, nullptr);

    // 4) softmax, in place
    softmax_kernel<<<NTOK, 256>>>();

    // 5) context (N=256 in one tile)
    gemm_kernel<2><<<dim3(SEQ / 128, 1, NBATCH), 256, SMEM_TOTAL>>>(
        nullptr, nullptr, nullptr, nullptr, nullptr, nullptr, out);
}